// round 1
// baseline (speedup 1.0000x reference)
#include <cuda_runtime.h>
#include <math.h>

#define SEQ   2048
#define HID   2048
#define HQ    16
#define HKV   4
#define DH    128
#define QBN   32      // number of 64-token blocks
#define BSZ   64
#define GHD   128
#define INTER 5632

#define SCALE_INV_SQRT_128 0.08838834764831845f

// ---------------- device scratch (static, no allocation) ----------------
__device__ float g_h   [SEQ*HID];
__device__ float g_q   [SEQ*HQ*DH];
__device__ float g_k   [SEQ*HKV*DH];
__device__ float g_v   [SEQ*HKV*DH];
__device__ float g_qp  [QBN*HQ*DH];
__device__ float g_kp  [QBN*HKV*DH];
__device__ float g_qg  [QBN*HQ*GHD];
__device__ float g_kg  [QBN*HKV*GHD];
__device__ unsigned char g_keep[HQ*QBN*QBN];
__device__ float g_o   [SEQ*HQ*DH];
__device__ float g_h2  [SEQ*HID];
__device__ float g_h3  [SEQ*HID];
__device__ float g_gate[SEQ*INTER];
__device__ float g_up  [SEQ*INTER];

// ---------------- RMSNorm ----------------
__global__ void rms_kernel(const float* __restrict__ x, const float* __restrict__ w,
                           float* __restrict__ out) {
    int row = blockIdx.x;
    const float* xr = x + (size_t)row * HID;
    float s = 0.f;
    for (int i = threadIdx.x; i < HID; i += 256) { float v = xr[i]; s += v * v; }
    __shared__ float red[256];
    red[threadIdx.x] = s; __syncthreads();
    for (int st = 128; st > 0; st >>= 1) {
        if (threadIdx.x < st) red[threadIdx.x] += red[threadIdx.x + st];
        __syncthreads();
    }
    float r = rsqrtf(red[0] / (float)HID + 1e-6f);
    for (int i = threadIdx.x; i < HID; i += 256)
        out[(size_t)row * HID + i] = w[i] * xr[i] * r;
}

// ---------------- generic SGEMM: C = A(MxK) @ B(KxN) [+bias][+res] ----------------
// requires M%128==0, N%128==0, K%8==0 (true for all call sites)
__global__ void __launch_bounds__(256) sgemm_kernel(
    const float* __restrict__ A, const float* __restrict__ B,
    const float* __restrict__ bias, const float* __restrict__ res,
    float* __restrict__ C, int M, int N, int K)
{
    __shared__ float As[8][128];
    __shared__ float Bs[8][128];
    const int tid = threadIdx.x;
    const int bx = blockIdx.x * 128;
    const int by = blockIdx.y * 128;
    const int tx = tid & 15;
    const int ty = tid >> 4;
    const int arow = tid >> 1;
    const int acol = (tid & 1) << 2;
    const int brow = tid >> 5;
    const int bcol = (tid & 31) << 2;

    const float* Ap = A + (size_t)(by + arow) * K + acol;
    const float* Bp = B + (size_t)brow * N + bx + bcol;

    float acc[8][8];
#pragma unroll
    for (int i = 0; i < 8; i++)
#pragma unroll
        for (int j = 0; j < 8; j++) acc[i][j] = 0.f;

    for (int k0 = 0; k0 < K; k0 += 8) {
        float4 av = *(const float4*)Ap;
        As[acol + 0][arow] = av.x;
        As[acol + 1][arow] = av.y;
        As[acol + 2][arow] = av.z;
        As[acol + 3][arow] = av.w;
        *(float4*)&Bs[brow][bcol] = *(const float4*)Bp;
        __syncthreads();
#pragma unroll
        for (int kk = 0; kk < 8; kk++) {
            float a[8], b[8];
            *(float4*)&a[0] = *(const float4*)&As[kk][ty * 8];
            *(float4*)&a[4] = *(const float4*)&As[kk][ty * 8 + 4];
            *(float4*)&b[0] = *(const float4*)&Bs[kk][tx * 8];
            *(float4*)&b[4] = *(const float4*)&Bs[kk][tx * 8 + 4];
#pragma unroll
            for (int i = 0; i < 8; i++)
#pragma unroll
                for (int j = 0; j < 8; j++)
                    acc[i][j] += a[i] * b[j];
        }
        __syncthreads();
        Ap += 8;
        Bp += (size_t)8 * N;
    }

    const int row0 = by + ty * 8;
    const int col0 = bx + tx * 8;
#pragma unroll
    for (int i = 0; i < 8; i++) {
#pragma unroll
        for (int j = 0; j < 8; j++) {
            float vv = acc[i][j];
            if (bias) vv += bias[col0 + j];
            if (res)  vv += res[(size_t)(row0 + i) * N + col0 + j];
            C[(size_t)(row0 + i) * N + col0 + j] = vv;
        }
    }
}

// ---------------- block-mean pooling over 64 tokens ----------------
// x: (SEQ, H, DH)  -> out: (QBN*H, DH) row = qb*H + h
__global__ void pool_kernel(const float* __restrict__ x, float* __restrict__ out, int H) {
    int qb = blockIdx.x, h = blockIdx.y, d = threadIdx.x;
    float s = 0.f;
    for (int i = 0; i < BSZ; i++)
        s += x[((size_t)(qb * BSZ + i) * H + h) * DH + d];
    out[((size_t)qb * H + h) * DH + d] = s * (1.f / (float)BSZ);
}

// ---------------- gate scores + softmax + keep mask ----------------
// qg: (QBN*HQ, GHD), kg: (QBN*HKV, GHD); keep: [HQ][QBN][QBN]
__global__ void gate_kernel(const float* __restrict__ qg, const float* __restrict__ kg,
                            unsigned char* __restrict__ keep) {
    int h = blockIdx.x, qb = blockIdx.y, kb = threadIdx.x; // 32 lanes
    const float* qv = qg + ((size_t)qb * HQ + h) * GHD;
    const float* kv = kg + ((size_t)kb * HKV + (h >> 2)) * GHD;
    float s = 0.f;
    for (int d = 0; d < GHD; d++) s += qv[d] * kv[d];
    s *= SCALE_INV_SQRT_128;
    if (kb > qb) s = -1e30f;
    // warp softmax over the 32 kb lanes
    float m = s;
    for (int off = 16; off > 0; off >>= 1)
        m = fmaxf(m, __shfl_xor_sync(0xffffffffu, m, off));
    float e = expf(s - m);
    float sum = e;
    for (int off = 16; off > 0; off >>= 1)
        sum += __shfl_xor_sync(0xffffffffu, sum, off);
    float gate = e / sum;
    bool kp = (kb <= qb) && ((gate >= 0.004f) || (kb == qb));
    keep[((size_t)h * QBN + qb) * QBN + kb] = kp ? 1 : 0;
}

// ---------------- RoPE (in place) ----------------
__global__ void rope_kernel(float* __restrict__ x, const float* __restrict__ cs,
                            const float* __restrict__ sn, int H) {
    int idx = blockIdx.x * blockDim.x + threadIdx.x; // SEQ*H*64 total
    int d = idx & 63;
    int h = (idx >> 6) % H;
    int s = idx / (64 * H);
    float* p = x + ((size_t)s * H + h) * DH;
    float x1 = p[d], x2 = p[d + 64];
    float c1 = cs[(size_t)s * DH + d],      s1 = sn[(size_t)s * DH + d];
    float c2 = cs[(size_t)s * DH + d + 64], s2 = sn[(size_t)s * DH + d + 64];
    p[d]      = x1 * c1 - x2 * s1;
    p[d + 64] = x2 * c2 + x1 * s2;
}

// ---------------- block-sparse flash attention ----------------
// grid (QBN, HQ), 256 threads. Per row r: 4 threads (c=0..3) own score cols
// c*16..c*16+15 and output dims c*32..c*32+31.
#define ATTN_SMEM_FLOATS (3 * 64 * 128 + 64 * 64 + 64 * 4 * 2)
__global__ void __launch_bounds__(256) attn_kernel(
    const float* __restrict__ q, const float* __restrict__ k, const float* __restrict__ v,
    const unsigned char* __restrict__ keep, float* __restrict__ o)
{
    extern __shared__ float sm[];
    float* Qs   = sm;                 // 64*128
    float* Ks   = Qs + 64 * 128;      // 64*128
    float* Vs   = Ks + 64 * 128;      // 64*128
    float* Ps   = Vs + 64 * 128;      // 64*64
    float* redm = Ps + 64 * 64;       // 64*4
    float* redl = redm + 256;         // 64*4

    const int qb = blockIdx.x, h = blockIdx.y;
    const int hk = h >> 2;
    const int tid = threadIdx.x;
    const int r = tid >> 2, c = tid & 3;

    for (int i = tid; i < 64 * 128; i += 256) {
        int rr = i >> 7, dd = i & 127;
        Qs[i] = q[((size_t)(qb * 64 + rr) * HQ + h) * DH + dd];
    }

    float m_i = -1e30f, l_i = 0.f;
    float acc[32];
#pragma unroll
    for (int d = 0; d < 32; d++) acc[d] = 0.f;

    const unsigned char* krow = keep + ((size_t)h * QBN + qb) * QBN;

    for (int kb = 0; kb <= qb; kb++) {
        if (!krow[kb]) continue;          // uniform across block
        __syncthreads();                  // protect Ks/Vs/Ps from prior reads
        for (int i = tid; i < 64 * 128; i += 256) {
            int rr = i >> 7, dd = i & 127;
            size_t gi = ((size_t)(kb * 64 + rr) * HKV + hk) * DH + dd;
            Ks[i] = k[gi];
            Vs[i] = v[gi];
        }
        __syncthreads();

        // scores for this thread's 16 columns
        float sc[16];
        float tmax = -1e30f;
        const float4* q4 = (const float4*)&Qs[r * 128];
#pragma unroll 4
        for (int j = 0; j < 16; j++) {
            int col = c * 16 + j;
            const float4* k4 = (const float4*)&Ks[col * 128];
            float s = 0.f;
#pragma unroll
            for (int d4 = 0; d4 < 32; d4++) {
                float4 a = q4[d4], b = k4[d4];
                s += a.x * b.x + a.y * b.y + a.z * b.z + a.w * b.w;
            }
            s *= SCALE_INV_SQRT_128;
            if (kb == qb && col > r) s = -1e30f;
            sc[j] = s;
            tmax = fmaxf(tmax, s);
        }
        redm[r * 4 + c] = tmax;
        __syncthreads();
        float newm = fmaxf(fmaxf(redm[r * 4 + 0], redm[r * 4 + 1]),
                           fmaxf(redm[r * 4 + 2], redm[r * 4 + 3]));
        newm = fmaxf(newm, m_i);
        float lsum = 0.f;
#pragma unroll
        for (int j = 0; j < 16; j++) {
            float p = __expf(sc[j] - newm);
            Ps[r * 64 + c * 16 + j] = p;
            lsum += p;
        }
        redl[r * 4 + c] = lsum;
        float alpha = __expf(m_i - newm);
#pragma unroll
        for (int d = 0; d < 32; d++) acc[d] *= alpha;
        m_i = newm;
        __syncthreads();
        l_i = l_i * alpha + (redl[r * 4 + 0] + redl[r * 4 + 1] +
                             redl[r * 4 + 2] + redl[r * 4 + 3]);
        // acc += P @ V   (this thread's 32 dims)
        for (int cc = 0; cc < 64; cc++) {
            float p = Ps[r * 64 + cc];
            const float4* v4 = (const float4*)&Vs[cc * 128 + c * 32];
#pragma unroll
            for (int d4 = 0; d4 < 8; d4++) {
                float4 vv = v4[d4];
                acc[d4 * 4 + 0] += p * vv.x;
                acc[d4 * 4 + 1] += p * vv.y;
                acc[d4 * 4 + 2] += p * vv.z;
                acc[d4 * 4 + 3] += p * vv.w;
            }
        }
    }

    float inv = 1.f / l_i;
#pragma unroll
    for (int d = 0; d < 32; d++)
        o[((size_t)(qb * 64 + r) * HQ + h) * DH + c * 32 + d] = acc[d] * inv;
}

// ---------------- SiLU(gate) * up  (in place into gate) ----------------
__global__ void silu_mul_kernel(float* __restrict__ g, const float* __restrict__ u) {
    int i = blockIdx.x * 256 + threadIdx.x;
    float x = g[i];
    g[i] = (x / (1.f + __expf(-x))) * u[i];
}

// ---------------- launch ----------------
extern "C" void kernel_launch(void* const* d_in, const int* in_sizes, int n_in,
                              void* d_out, int out_size) {
    const float* hidden = (const float*)d_in[0];
    const float* cosp   = (const float*)d_in[1];
    const float* sinp   = (const float*)d_in[2];
    const float* ln1    = (const float*)d_in[3];
    const float* ln2    = (const float*)d_in[4];
    const float* Wq     = (const float*)d_in[5];
    const float* bq     = (const float*)d_in[6];
    const float* Wk     = (const float*)d_in[7];
    const float* bk     = (const float*)d_in[8];
    const float* Wv     = (const float*)d_in[9];
    const float* bv     = (const float*)d_in[10];
    const float* Wo     = (const float*)d_in[11];
    const float* gWq    = (const float*)d_in[12];
    const float* gWk    = (const float*)d_in[13];
    const float* Wgate  = (const float*)d_in[14];
    const float* Wup    = (const float*)d_in[15];
    const float* Wdown  = (const float*)d_in[16];
    float* out = (float*)d_out;

    float *h, *q, *k, *v, *qp, *kp, *qg, *kg, *o, *h2, *h3, *gt, *up;
    unsigned char* keep;
    cudaGetSymbolAddress((void**)&h,   g_h);
    cudaGetSymbolAddress((void**)&q,   g_q);
    cudaGetSymbolAddress((void**)&k,   g_k);
    cudaGetSymbolAddress((void**)&v,   g_v);
    cudaGetSymbolAddress((void**)&qp,  g_qp);
    cudaGetSymbolAddress((void**)&kp,  g_kp);
    cudaGetSymbolAddress((void**)&qg,  g_qg);
    cudaGetSymbolAddress((void**)&kg,  g_kg);
    cudaGetSymbolAddress((void**)&keep, g_keep);
    cudaGetSymbolAddress((void**)&o,   g_o);
    cudaGetSymbolAddress((void**)&h2,  g_h2);
    cudaGetSymbolAddress((void**)&h3,  g_h3);
    cudaGetSymbolAddress((void**)&gt,  g_gate);
    cudaGetSymbolAddress((void**)&up,  g_up);

    // 1) h = rms(hidden) * ln1
    rms_kernel<<<SEQ, 256>>>(hidden, ln1, h);

    // 2) q/k/v projections
    sgemm_kernel<<<dim3((HQ*DH)/128, SEQ/128), 256>>>(h, Wq, bq, nullptr, q, SEQ, HQ*DH, HID);
    sgemm_kernel<<<dim3((HKV*DH)/128, SEQ/128), 256>>>(h, Wk, bk, nullptr, k, SEQ, HKV*DH, HID);
    sgemm_kernel<<<dim3((HKV*DH)/128, SEQ/128), 256>>>(h, Wv, bv, nullptr, v, SEQ, HKV*DH, HID);

    // 3) gate path (pool pre-RoPE, then tiny GEMMs)
    pool_kernel<<<dim3(QBN, HQ), DH>>>(q, qp, HQ);
    pool_kernel<<<dim3(QBN, HKV), DH>>>(k, kp, HKV);
    sgemm_kernel<<<dim3(GHD/128, (QBN*HQ)/128), 256>>>(qp, gWq, nullptr, nullptr, qg, QBN*HQ, GHD, DH);
    sgemm_kernel<<<dim3(GHD/128, (QBN*HKV)/128), 256>>>(kp, gWk, nullptr, nullptr, kg, QBN*HKV, GHD, DH);
    gate_kernel<<<dim3(HQ, QBN), 32>>>(qg, kg, keep);

    // 4) RoPE in place
    rope_kernel<<<(SEQ*HQ*64)/256, 256>>>(q, cosp, sinp, HQ);
    rope_kernel<<<(SEQ*HKV*64)/256, 256>>>(k, cosp, sinp, HKV);

    // 5) block-sparse flash attention
    cudaFuncSetAttribute(attn_kernel, cudaFuncAttributeMaxDynamicSharedMemorySize,
                         ATTN_SMEM_FLOATS * (int)sizeof(float));
    attn_kernel<<<dim3(QBN, HQ), 256, ATTN_SMEM_FLOATS * (int)sizeof(float)>>>(q, k, v, keep, o);

    // 6) h2 = o @ Wo + hidden
    sgemm_kernel<<<dim3(HID/128, SEQ/128), 256>>>(o, Wo, nullptr, hidden, h2, SEQ, HID, HQ*DH);

    // 7) h3 = rms(h2) * ln2
    rms_kernel<<<SEQ, 256>>>(h2, ln2, h3);

    // 8) MLP
    sgemm_kernel<<<dim3(INTER/128, SEQ/128), 256>>>(h3, Wgate, nullptr, nullptr, gt, SEQ, INTER, HID);
    sgemm_kernel<<<dim3(INTER/128, SEQ/128), 256>>>(h3, Wup,   nullptr, nullptr, up, SEQ, INTER, HID);
    silu_mul_kernel<<<(SEQ*INTER)/256, 256>>>(gt, up);

    // 9) out = gt @ Wdown + h2
    sgemm_kernel<<<dim3(HID/128, SEQ/128), 256>>>(gt, Wdown, nullptr, h2, out, SEQ, HID, INTER);
}

// round 3
// speedup vs baseline: 1.4234x; 1.4234x over previous
#include <cuda_runtime.h>
#include <cuda_bf16.h>
#include <math.h>
#include <stdint.h>

#define SEQ   2048
#define HID   2048
#define HQ    16
#define HKV   4
#define DH    128
#define QBN   32
#define BSZ   64
#define GHD   128
#define INTER 5632

#define SCALE_INV_SQRT_128 0.08838834764831845f

// ================= helpers =================
__device__ __forceinline__ uint32_t smem_u32(const void* p) {
    uint32_t a;
    asm("{ .reg .u64 t; cvta.to.shared.u64 t, %1; cvt.u32.u64 %0, t; }" : "=r"(a) : "l"(p));
    return a;
}
__device__ __forceinline__ void cp_async16(uint32_t saddr, const void* gptr) {
    asm volatile("cp.async.cg.shared.global [%0], [%1], 16;" :: "r"(saddr), "l"(gptr));
}
__device__ __forceinline__ void cp_commit() { asm volatile("cp.async.commit_group;"); }

#define LDSM_X4(r0, r1, r2, r3, addr) \
    asm volatile("ldmatrix.sync.aligned.m8n8.x4.shared.b16 {%0,%1,%2,%3}, [%4];" \
        : "=r"(r0), "=r"(r1), "=r"(r2), "=r"(r3) : "r"(addr))

#define MMA16816(c, a, b0r, b1r) \
    asm volatile("mma.sync.aligned.m16n8k16.row.col.f32.bf16.bf16.f32 " \
        "{%0,%1,%2,%3}, {%4,%5,%6,%7}, {%8,%9}, {%0,%1,%2,%3};" \
        : "+f"((c)[0]), "+f"((c)[1]), "+f"((c)[2]), "+f"((c)[3]) \
        : "r"((a)[0]), "r"((a)[1]), "r"((a)[2]), "r"((a)[3]), "r"(b0r), "r"(b1r))

static __device__ __forceinline__ uint32_t sw128(uint32_t o) { return o ^ ((o >> 3) & 0x70); }

// ================= device scratch =================
__device__ float g_h   [SEQ*HID];
__device__ float g_q   [SEQ*HQ*DH];
__device__ float g_k   [SEQ*HKV*DH];
__device__ float g_v   [SEQ*HKV*DH];
__device__ float g_qp  [QBN*HQ*DH];
__device__ float g_kp  [QBN*HKV*DH];
__device__ float g_qg  [QBN*HQ*GHD];
__device__ float g_kg  [QBN*HKV*GHD];
__device__ unsigned char g_keep[HQ*QBN*QBN];
__device__ float g_o   [SEQ*HQ*DH];
__device__ float g_h2  [SEQ*HID];
__device__ float g_h3  [SEQ*HID];
__device__ float g_gate[SEQ*INTER];
__device__ float g_up  [SEQ*INTER];

// bf16 hi/lo-split copies: A-side [M, 2K], B-side [N, 2K] (hi block | lo block)
__device__ __nv_bfloat16 g_Wq2[2048*4096];
__device__ __nv_bfloat16 g_Wk2[512*4096];
__device__ __nv_bfloat16 g_Wv2[512*4096];
__device__ __nv_bfloat16 g_Wo2[2048*4096];
__device__ __nv_bfloat16 g_Wg2[5632*4096];
__device__ __nv_bfloat16 g_Wu2[5632*4096];
__device__ __nv_bfloat16 g_Wd2[2048*11264];
__device__ __nv_bfloat16 g_ha2 [2048*4096];
__device__ __nv_bfloat16 g_oa2 [2048*4096];
__device__ __nv_bfloat16 g_h3a2[2048*4096];
__device__ __nv_bfloat16 g_gt2 [2048*11264];

// ================= conversion kernels =================
__global__ void aconv_kernel(const float* __restrict__ x, __nv_bfloat16* __restrict__ y, int K) {
    int m = blockIdx.y;
    int k = blockIdx.x * 256 + threadIdx.x;
    float v = x[(size_t)m * K + k];
    __nv_bfloat16 h = __float2bfloat16(v);
    float lo = v - __bfloat162float(h);
    size_t base = (size_t)m * 2 * K;
    y[base + k]     = h;
    y[base + K + k] = __float2bfloat16(lo);
}

__global__ void wconv_kernel(const float* __restrict__ W, __nv_bfloat16* __restrict__ y,
                             int K, int N) {
    __shared__ float tile[32][33];
    int n0 = blockIdx.x * 32, k0 = blockIdx.y * 32;
    for (int i = threadIdx.y; i < 32; i += 8)
        tile[i][threadIdx.x] = W[(size_t)(k0 + i) * N + n0 + threadIdx.x];
    __syncthreads();
    for (int i = threadIdx.y; i < 32; i += 8) {
        int n = n0 + i, k = k0 + threadIdx.x;
        float v = tile[threadIdx.x][i];
        __nv_bfloat16 h = __float2bfloat16(v);
        float lo = v - __bfloat162float(h);
        size_t base = (size_t)n * 2 * K;
        y[base + k]     = h;
        y[base + K + k] = __float2bfloat16(lo);
    }
}

// ================= bf16 HMMA GEMM (3-segment hi/lo compensated) =================
// C[M,N] fp32 = A x B^T where A2[M,2K], B2[N,2K] are (hi|lo) splits.
// Segments: (Ahi,Bhi), (Alo,Bhi), (Ahi,Blo)  => err ~ 2^-16.
// CTA tile 128x128, BK=64, 8 warps 2x4, warp tile 64x32, double-buffered cp.async.
#define HG_SMEM 65536

__global__ void __launch_bounds__(256, 2) hgemm_kernel(
    const __nv_bfloat16* __restrict__ A, const __nv_bfloat16* __restrict__ B,
    const float* __restrict__ bias, const float* __restrict__ res,
    float* __restrict__ C, int N, int K)
{
    extern __shared__ char smraw[];
    const uint32_t smu = smem_u32(smraw);
    const int tid = threadIdx.x;
    const int lane = tid & 31, wid = tid >> 5;
    const int wm = wid >> 2, wn = wid & 3;
    const size_t lda = 2 * (size_t)K;
    const int kpseg = K >> 6;
    const int nch = 3 * kpseg;
    const size_t arow0 = (size_t)blockIdx.x * 128;
    const size_t brow0 = (size_t)blockIdx.y * 128;

    float acc[4][4][4];
#pragma unroll
    for (int i = 0; i < 4; i++)
#pragma unroll
        for (int j = 0; j < 4; j++)
#pragma unroll
            for (int t = 0; t < 4; t++) acc[i][j][t] = 0.f;

    auto issue = [&](int ch, int b) {
        int seg = ch / kpseg;
        int kk = (ch - seg * kpseg) << 6;
        const __nv_bfloat16* Ab = A + (seg == 1 ? K : 0) + kk;
        const __nv_bfloat16* Bb = B + (seg == 2 ? K : 0) + kk;
        uint32_t abase = smu + b * 32768;
        uint32_t bbase = abase + 16384;
#pragma unroll
        for (int i = 0; i < 4; i++) {
            int u = i * 256 + tid;
            int r = u >> 3, c = u & 7;
            uint32_t so = sw128((uint32_t)(r * 128 + c * 16));
            cp_async16(abase + so, Ab + (arow0 + r) * lda + c * 8);
            cp_async16(bbase + so, Bb + (brow0 + r) * lda + c * 8);
        }
        cp_commit();
    };

    issue(0, 0);

    for (int ch = 0; ch < nch; ch++) {
        const int b = ch & 1;
        if (ch + 1 < nch) {
            issue(ch + 1, b ^ 1);
            asm volatile("cp.async.wait_group 1;");
        } else {
            asm volatile("cp.async.wait_group 0;");
        }
        __syncthreads();

        const uint32_t abuf = smu + b * 32768;
        const uint32_t bbuf = abuf + 16384;
        const int arow = (wm << 6) + (lane & 15);
        const int brow = (wn << 5) + (lane & 15);
        const int kbl = (lane >> 4) * 16;

#pragma unroll
        for (int ks = 0; ks < 4; ks++) {
            const int kb = ks * 32 + kbl;
            uint32_t a[4][4];
#pragma unroll
            for (int mt = 0; mt < 4; mt++) {
                uint32_t off = (uint32_t)((arow + (mt << 4)) * 128 + kb);
                LDSM_X4(a[mt][0], a[mt][1], a[mt][2], a[mt][3], abuf + sw128(off));
            }
            uint32_t bf[4][2];
#pragma unroll
            for (int nt2 = 0; nt2 < 2; nt2++) {
                uint32_t t0, t1, t2, t3;
                uint32_t off = (uint32_t)((brow + (nt2 << 4)) * 128 + kb);
                LDSM_X4(t0, t1, t2, t3, bbuf + sw128(off));
                bf[nt2 * 2 + 0][0] = t0; bf[nt2 * 2 + 0][1] = t2;
                bf[nt2 * 2 + 1][0] = t1; bf[nt2 * 2 + 1][1] = t3;
            }
#pragma unroll
            for (int mt = 0; mt < 4; mt++)
#pragma unroll
                for (int nt = 0; nt < 4; nt++)
                    MMA16816(acc[mt][nt], a[mt], bf[nt][0], bf[nt][1]);
        }
        __syncthreads();
    }

    // epilogue
    const int rbase = (int)arow0 + (wm << 6) + (lane >> 2);
    const int cbase = (int)brow0 + (wn << 5) + ((lane & 3) << 1);
#pragma unroll
    for (int nt = 0; nt < 4; nt++) {
        const int col = cbase + (nt << 3);
        float b0 = bias ? bias[col] : 0.f;
        float b1 = bias ? bias[col + 1] : 0.f;
#pragma unroll
        for (int mt = 0; mt < 4; mt++) {
            const int row = rbase + (mt << 4);
            size_t gi = (size_t)row * N + col;
            float v0 = acc[mt][nt][0] + b0, v1 = acc[mt][nt][1] + b1;
            if (res) { v0 += res[gi]; v1 += res[gi + 1]; }
            *(float2*)(C + gi) = make_float2(v0, v1);
            size_t gi2 = gi + (size_t)8 * N;
            float v2 = acc[mt][nt][2] + b0, v3 = acc[mt][nt][3] + b1;
            if (res) { v2 += res[gi2]; v3 += res[gi2 + 1]; }
            *(float2*)(C + gi2) = make_float2(v2, v3);
        }
    }
}

// ================= RMSNorm =================
__global__ void rms_kernel(const float* __restrict__ x, const float* __restrict__ w,
                           float* __restrict__ out) {
    int row = blockIdx.x;
    const float* xr = x + (size_t)row * HID;
    float s = 0.f;
    for (int i = threadIdx.x; i < HID; i += 256) { float v = xr[i]; s += v * v; }
    __shared__ float red[256];
    red[threadIdx.x] = s; __syncthreads();
    for (int st = 128; st > 0; st >>= 1) {
        if (threadIdx.x < st) red[threadIdx.x] += red[threadIdx.x + st];
        __syncthreads();
    }
    float r = rsqrtf(red[0] / (float)HID + 1e-6f);
    for (int i = threadIdx.x; i < HID; i += 256)
        out[(size_t)row * HID + i] = w[i] * xr[i] * r;
}

// ================= small fp32 SGEMM (gate path only) =================
__global__ void __launch_bounds__(256) sgemm_kernel(
    const float* __restrict__ A, const float* __restrict__ B,
    const float* __restrict__ bias, const float* __restrict__ res,
    float* __restrict__ C, int M, int N, int K)
{
    __shared__ float As[8][128];
    __shared__ float Bs[8][128];
    const int tid = threadIdx.x;
    const int bx = blockIdx.x * 128;
    const int by = blockIdx.y * 128;
    const int tx = tid & 15;
    const int ty = tid >> 4;
    const int arow = tid >> 1;
    const int acol = (tid & 1) << 2;
    const int brow = tid >> 5;
    const int bcol = (tid & 31) << 2;

    const float* Ap = A + (size_t)(by + arow) * K + acol;
    const float* Bp = B + (size_t)brow * N + bx + bcol;

    float acc[8][8];
#pragma unroll
    for (int i = 0; i < 8; i++)
#pragma unroll
        for (int j = 0; j < 8; j++) acc[i][j] = 0.f;

    for (int k0 = 0; k0 < K; k0 += 8) {
        float4 av = *(const float4*)Ap;
        As[acol + 0][arow] = av.x;
        As[acol + 1][arow] = av.y;
        As[acol + 2][arow] = av.z;
        As[acol + 3][arow] = av.w;
        *(float4*)&Bs[brow][bcol] = *(const float4*)Bp;
        __syncthreads();
#pragma unroll
        for (int kk = 0; kk < 8; kk++) {
            float a[8], bb[8];
            *(float4*)&a[0] = *(const float4*)&As[kk][ty * 8];
            *(float4*)&a[4] = *(const float4*)&As[kk][ty * 8 + 4];
            *(float4*)&bb[0] = *(const float4*)&Bs[kk][tx * 8];
            *(float4*)&bb[4] = *(const float4*)&Bs[kk][tx * 8 + 4];
#pragma unroll
            for (int i = 0; i < 8; i++)
#pragma unroll
                for (int j = 0; j < 8; j++)
                    acc[i][j] += a[i] * bb[j];
        }
        __syncthreads();
        Ap += 8;
        Bp += (size_t)8 * N;
    }

    const int row0 = by + ty * 8;
    const int col0 = bx + tx * 8;
#pragma unroll
    for (int i = 0; i < 8; i++) {
#pragma unroll
        for (int j = 0; j < 8; j++) {
            float vv = acc[i][j];
            if (bias) vv += bias[col0 + j];
            if (res)  vv += res[(size_t)(row0 + i) * N + col0 + j];
            C[(size_t)(row0 + i) * N + col0 + j] = vv;
        }
    }
}

// ================= pooling / gate / rope / attn / silu =================
__global__ void pool_kernel(const float* __restrict__ x, float* __restrict__ out, int H) {
    int qb = blockIdx.x, h = blockIdx.y, d = threadIdx.x;
    float s = 0.f;
    for (int i = 0; i < BSZ; i++)
        s += x[((size_t)(qb * BSZ + i) * H + h) * DH + d];
    out[((size_t)qb * H + h) * DH + d] = s * (1.f / (float)BSZ);
}

__global__ void gate_kernel(const float* __restrict__ qg, const float* __restrict__ kg,
                            unsigned char* __restrict__ keep) {
    int h = blockIdx.x, qb = blockIdx.y, kb = threadIdx.x;
    const float* qv = qg + ((size_t)qb * HQ + h) * GHD;
    const float* kv = kg + ((size_t)kb * HKV + (h >> 2)) * GHD;
    float s = 0.f;
    for (int d = 0; d < GHD; d++) s += qv[d] * kv[d];
    s *= SCALE_INV_SQRT_128;
    if (kb > qb) s = -1e30f;
    float m = s;
    for (int off = 16; off > 0; off >>= 1)
        m = fmaxf(m, __shfl_xor_sync(0xffffffffu, m, off));
    float e = expf(s - m);
    float sum = e;
    for (int off = 16; off > 0; off >>= 1)
        sum += __shfl_xor_sync(0xffffffffu, sum, off);
    float gate = e / sum;
    bool kp = (kb <= qb) && ((gate >= 0.004f) || (kb == qb));
    keep[((size_t)h * QBN + qb) * QBN + kb] = kp ? 1 : 0;
}

__global__ void rope_kernel(float* __restrict__ x, const float* __restrict__ cs,
                            const float* __restrict__ sn, int H) {
    int idx = blockIdx.x * blockDim.x + threadIdx.x;
    int d = idx & 63;
    int h = (idx >> 6) % H;
    int s = idx / (64 * H);
    float* p = x + ((size_t)s * H + h) * DH;
    float x1 = p[d], x2 = p[d + 64];
    float c1 = cs[(size_t)s * DH + d],      s1 = sn[(size_t)s * DH + d];
    float c2 = cs[(size_t)s * DH + d + 64], s2 = sn[(size_t)s * DH + d + 64];
    p[d]      = x1 * c1 - x2 * s1;
    p[d + 64] = x2 * c2 + x1 * s2;
}

#define ATTN_SMEM_FLOATS (3 * 64 * 128 + 64 * 64 + 64 * 4 * 2)
__global__ void __launch_bounds__(256) attn_kernel(
    const float* __restrict__ q, const float* __restrict__ k, const float* __restrict__ v,
    const unsigned char* __restrict__ keep, float* __restrict__ o)
{
    extern __shared__ float smf[];
    float* Qs   = smf;
    float* Ks   = Qs + 64 * 128;
    float* Vs   = Ks + 64 * 128;
    float* Ps   = Vs + 64 * 128;
    float* redm = Ps + 64 * 64;
    float* redl = redm + 256;

    const int qb = blockIdx.x, h = blockIdx.y;
    const int hk = h >> 2;
    const int tid = threadIdx.x;
    const int r = tid >> 2, c = tid & 3;

    for (int i = tid; i < 64 * 128; i += 256) {
        int rr = i >> 7, dd = i & 127;
        Qs[i] = q[((size_t)(qb * 64 + rr) * HQ + h) * DH + dd];
    }

    float m_i = -1e30f, l_i = 0.f;
    float acc[32];
#pragma unroll
    for (int d = 0; d < 32; d++) acc[d] = 0.f;

    const unsigned char* krow = keep + ((size_t)h * QBN + qb) * QBN;

    for (int kb = 0; kb <= qb; kb++) {
        if (!krow[kb]) continue;
        __syncthreads();
        for (int i = tid; i < 64 * 128; i += 256) {
            int rr = i >> 7, dd = i & 127;
            size_t gi = ((size_t)(kb * 64 + rr) * HKV + hk) * DH + dd;
            Ks[i] = k[gi];
            Vs[i] = v[gi];
        }
        __syncthreads();

        float sc[16];
        float tmax = -1e30f;
        const float4* q4 = (const float4*)&Qs[r * 128];
#pragma unroll 4
        for (int j = 0; j < 16; j++) {
            int col = c * 16 + j;
            const float4* k4 = (const float4*)&Ks[col * 128];
            float s = 0.f;
#pragma unroll
            for (int d4 = 0; d4 < 32; d4++) {
                float4 a = q4[d4], bb = k4[d4];
                s += a.x * bb.x + a.y * bb.y + a.z * bb.z + a.w * bb.w;
            }
            s *= SCALE_INV_SQRT_128;
            if (kb == qb && col > r) s = -1e30f;
            sc[j] = s;
            tmax = fmaxf(tmax, s);
        }
        redm[r * 4 + c] = tmax;
        __syncthreads();
        float newm = fmaxf(fmaxf(redm[r * 4 + 0], redm[r * 4 + 1]),
                           fmaxf(redm[r * 4 + 2], redm[r * 4 + 3]));
        newm = fmaxf(newm, m_i);
        float lsum = 0.f;
#pragma unroll
        for (int j = 0; j < 16; j++) {
            float p = __expf(sc[j] - newm);
            Ps[r * 64 + c * 16 + j] = p;
            lsum += p;
        }
        redl[r * 4 + c] = lsum;
        float alpha = __expf(m_i - newm);
#pragma unroll
        for (int d = 0; d < 32; d++) acc[d] *= alpha;
        m_i = newm;
        __syncthreads();
        l_i = l_i * alpha + (redl[r * 4 + 0] + redl[r * 4 + 1] +
                             redl[r * 4 + 2] + redl[r * 4 + 3]);
        for (int cc = 0; cc < 64; cc++) {
            float p = Ps[r * 64 + cc];
            const float4* v4 = (const float4*)&Vs[cc * 128 + c * 32];
#pragma unroll
            for (int d4 = 0; d4 < 8; d4++) {
                float4 vv = v4[d4];
                acc[d4 * 4 + 0] += p * vv.x;
                acc[d4 * 4 + 1] += p * vv.y;
                acc[d4 * 4 + 2] += p * vv.z;
                acc[d4 * 4 + 3] += p * vv.w;
            }
        }
    }

    float inv = 1.f / l_i;
#pragma unroll
    for (int d = 0; d < 32; d++)
        o[((size_t)(qb * 64 + r) * HQ + h) * DH + c * 32 + d] = acc[d] * inv;
}

__global__ void silu_mul_kernel(float* __restrict__ g, const float* __restrict__ u) {
    int i = blockIdx.x * 256 + threadIdx.x;
    float x = g[i];
    g[i] = (x / (1.f + __expf(-x))) * u[i];
}

// ================= launch =================
extern "C" void kernel_launch(void* const* d_in, const int* in_sizes, int n_in,
                              void* d_out, int out_size) {
    const float* hidden = (const float*)d_in[0];
    const float* cosp   = (const float*)d_in[1];
    const float* sinp   = (const float*)d_in[2];
    const float* ln1    = (const float*)d_in[3];
    const float* ln2    = (const float*)d_in[4];
    const float* Wq     = (const float*)d_in[5];
    const float* bq     = (const float*)d_in[6];
    const float* Wk     = (const float*)d_in[7];
    const float* bk     = (const float*)d_in[8];
    const float* Wv     = (const float*)d_in[9];
    const float* bv     = (const float*)d_in[10];
    const float* Wo     = (const float*)d_in[11];
    const float* gWq    = (const float*)d_in[12];
    const float* gWk    = (const float*)d_in[13];
    const float* Wgate  = (const float*)d_in[14];
    const float* Wup    = (const float*)d_in[15];
    const float* Wdown  = (const float*)d_in[16];
    float* out = (float*)d_out;

    float *h, *q, *k, *v, *qp, *kp, *qg, *kg, *o, *h2, *h3, *gt, *up;
    unsigned char* keep;
    __nv_bfloat16 *Wq2, *Wk2, *Wv2, *Wo2, *Wg2, *Wu2, *Wd2, *ha2, *oa2, *h3a2, *gt2;
    cudaGetSymbolAddress((void**)&h,   g_h);
    cudaGetSymbolAddress((void**)&q,   g_q);
    cudaGetSymbolAddress((void**)&k,   g_k);
    cudaGetSymbolAddress((void**)&v,   g_v);
    cudaGetSymbolAddress((void**)&qp,  g_qp);
    cudaGetSymbolAddress((void**)&kp,  g_kp);
    cudaGetSymbolAddress((void**)&qg,  g_qg);
    cudaGetSymbolAddress((void**)&kg,  g_kg);
    cudaGetSymbolAddress((void**)&keep, g_keep);
    cudaGetSymbolAddress((void**)&o,   g_o);
    cudaGetSymbolAddress((void**)&h2,  g_h2);
    cudaGetSymbolAddress((void**)&h3,  g_h3);
    cudaGetSymbolAddress((void**)&gt,  g_gate);
    cudaGetSymbolAddress((void**)&up,  g_up);
    cudaGetSymbolAddress((void**)&Wq2, g_Wq2);
    cudaGetSymbolAddress((void**)&Wk2, g_Wk2);
    cudaGetSymbolAddress((void**)&Wv2, g_Wv2);
    cudaGetSymbolAddress((void**)&Wo2, g_Wo2);
    cudaGetSymbolAddress((void**)&Wg2, g_Wg2);
    cudaGetSymbolAddress((void**)&Wu2, g_Wu2);
    cudaGetSymbolAddress((void**)&Wd2, g_Wd2);
    cudaGetSymbolAddress((void**)&ha2, g_ha2);
    cudaGetSymbolAddress((void**)&oa2, g_oa2);
    cudaGetSymbolAddress((void**)&h3a2, g_h3a2);
    cudaGetSymbolAddress((void**)&gt2, g_gt2);

    cudaFuncSetAttribute(hgemm_kernel, cudaFuncAttributeMaxDynamicSharedMemorySize, HG_SMEM);
    cudaFuncSetAttribute(attn_kernel, cudaFuncAttributeMaxDynamicSharedMemorySize,
                         ATTN_SMEM_FLOATS * (int)sizeof(float));

    dim3 w8(32, 8);

    // weight conversions (fp32 [K,N] -> bf16 split [N,2K])
    wconv_kernel<<<dim3(HID/32, HID/32),  w8>>>(Wq,    Wq2, HID,  HID);
    wconv_kernel<<<dim3(512/32, HID/32),  w8>>>(Wk,    Wk2, HID,  512);
    wconv_kernel<<<dim3(512/32, HID/32),  w8>>>(Wv,    Wv2, HID,  512);
    wconv_kernel<<<dim3(HID/32, HID/32),  w8>>>(Wo,    Wo2, HID,  HID);
    wconv_kernel<<<dim3(INTER/32, HID/32), w8>>>(Wgate, Wg2, HID,  INTER);
    wconv_kernel<<<dim3(INTER/32, HID/32), w8>>>(Wup,   Wu2, HID,  INTER);
    wconv_kernel<<<dim3(HID/32, INTER/32), w8>>>(Wdown, Wd2, INTER, HID);

    // 1) h = rms(hidden) * ln1 ; convert
    rms_kernel<<<SEQ, 256>>>(hidden, ln1, h);
    aconv_kernel<<<dim3(HID/256, SEQ), 256>>>(h, ha2, HID);

    // 2) q/k/v projections (tensor pipe)
    hgemm_kernel<<<dim3(SEQ/128, (HQ*DH)/128), 256, HG_SMEM>>>(ha2, Wq2, bq, nullptr, q, HQ*DH, HID);
    hgemm_kernel<<<dim3(SEQ/128, (HKV*DH)/128), 256, HG_SMEM>>>(ha2, Wk2, bk, nullptr, k, HKV*DH, HID);
    hgemm_kernel<<<dim3(SEQ/128, (HKV*DH)/128), 256, HG_SMEM>>>(ha2, Wv2, bv, nullptr, v, HKV*DH, HID);

    // 3) gate path
    pool_kernel<<<dim3(QBN, HQ), DH>>>(q, qp, HQ);
    pool_kernel<<<dim3(QBN, HKV), DH>>>(k, kp, HKV);
    sgemm_kernel<<<dim3(GHD/128, (QBN*HQ)/128), 256>>>(qp, gWq, nullptr, nullptr, qg, QBN*HQ, GHD, DH);
    sgemm_kernel<<<dim3(GHD/128, (QBN*HKV)/128), 256>>>(kp, gWk, nullptr, nullptr, kg, QBN*HKV, GHD, DH);
    gate_kernel<<<dim3(HQ, QBN), 32>>>(qg, kg, keep);

    // 4) RoPE in place
    rope_kernel<<<(SEQ*HQ*64)/256, 256>>>(q, cosp, sinp, HQ);
    rope_kernel<<<(SEQ*HKV*64)/256, 256>>>(k, cosp, sinp, HKV);

    // 5) block-sparse flash attention
    attn_kernel<<<dim3(QBN, HQ), 256, ATTN_SMEM_FLOATS * (int)sizeof(float)>>>(q, k, v, keep, o);

    // 6) h2 = o @ Wo + hidden
    aconv_kernel<<<dim3((HQ*DH)/256, SEQ), 256>>>(o, oa2, HQ*DH);
    hgemm_kernel<<<dim3(SEQ/128, HID/128), 256, HG_SMEM>>>(oa2, Wo2, nullptr, hidden, h2, HID, HQ*DH);

    // 7) h3 = rms(h2) * ln2
    rms_kernel<<<SEQ, 256>>>(h2, ln2, h3);
    aconv_kernel<<<dim3(HID/256, SEQ), 256>>>(h3, h3a2, HID);

    // 8) MLP
    hgemm_kernel<<<dim3(SEQ/128, INTER/128), 256, HG_SMEM>>>(h3a2, Wg2, nullptr, nullptr, gt, INTER, HID);
    hgemm_kernel<<<dim3(SEQ/128, INTER/128), 256, HG_SMEM>>>(h3a2, Wu2, nullptr, nullptr, up, INTER, HID);
    silu_mul_kernel<<<(SEQ*INTER)/256, 256>>>(gt, up);
    aconv_kernel<<<dim3(INTER/256, SEQ), 256>>>(gt, gt2, INTER);

    // 9) out = gt @ Wdown + h2
    hgemm_kernel<<<dim3(SEQ/128, HID/128), 256, HG_SMEM>>>(gt2, Wd2, nullptr, h2, out, HID, INTER);
}

// round 4
// speedup vs baseline: 1.4851x; 1.0433x over previous
#include <cuda_runtime.h>
#include <cuda_bf16.h>
#include <math.h>
#include <stdint.h>

#define SEQ   2048
#define HID   2048
#define HQ    16
#define HKV   4
#define DH    128
#define QBN   32
#define BSZ   64
#define GHD   128
#define INTER 5632
#define NQKV  3072            // 2048 q | 512 k | 512 v
#define NGU   11264           // 5632 gate | 5632 up

#define SCALE_INV_SQRT_128 0.08838834764831845f

// ================= helpers =================
__device__ __forceinline__ uint32_t smem_u32(const void* p) {
    uint32_t a;
    asm("{ .reg .u64 t; cvta.to.shared.u64 t, %1; cvt.u32.u64 %0, t; }" : "=r"(a) : "l"(p));
    return a;
}
__device__ __forceinline__ void cp_async16(uint32_t saddr, const void* gptr) {
    asm volatile("cp.async.cg.shared.global [%0], [%1], 16;" :: "r"(saddr), "l"(gptr));
}
__device__ __forceinline__ void cp_commit() { asm volatile("cp.async.commit_group;"); }

#define LDSM_X4(r0, r1, r2, r3, addr) \
    asm volatile("ldmatrix.sync.aligned.m8n8.x4.shared.b16 {%0,%1,%2,%3}, [%4];" \
        : "=r"(r0), "=r"(r1), "=r"(r2), "=r"(r3) : "r"(addr))

#define MMA16816(c, a, b0r, b1r) \
    asm volatile("mma.sync.aligned.m16n8k16.row.col.f32.bf16.bf16.f32 " \
        "{%0,%1,%2,%3}, {%4,%5,%6,%7}, {%8,%9}, {%0,%1,%2,%3};" \
        : "+f"((c)[0]), "+f"((c)[1]), "+f"((c)[2]), "+f"((c)[3]) \
        : "r"((a)[0]), "r"((a)[1]), "r"((a)[2]), "r"((a)[3]), "r"(b0r), "r"(b1r))

static __device__ __forceinline__ uint32_t sw128(uint32_t o) { return o ^ ((o >> 3) & 0x70); }

__device__ __forceinline__ void split_store(float v, __nv_bfloat16* hi, __nv_bfloat16* lo) {
    __nv_bfloat16 h = __float2bfloat16(v);
    *hi = h;
    *lo = __float2bfloat16(v - __bfloat162float(h));
}

// ================= device scratch =================
__device__ float g_qkv [SEQ*NQKV];      // q | k | v per row
__device__ float g_qp  [QBN*HQ*DH];
__device__ float g_kp  [QBN*HKV*DH];
__device__ float g_qg  [QBN*HQ*GHD];
__device__ float g_kg  [QBN*HKV*GHD];
__device__ unsigned char g_keep[HQ*QBN*QBN];
__device__ float g_h2  [SEQ*HID];
__device__ float g_gu  [SEQ*NGU];       // gate | up

__device__ __nv_bfloat16 g_Wqkv2[NQKV*4096];
__device__ __nv_bfloat16 g_Wo2  [2048*4096];
__device__ __nv_bfloat16 g_Wgu2 [NGU*4096];
__device__ __nv_bfloat16 g_Wd2  [2048*11264];
__device__ __nv_bfloat16 g_ha2  [2048*4096];
__device__ __nv_bfloat16 g_oa2  [2048*4096];
__device__ __nv_bfloat16 g_h3a2 [2048*4096];
__device__ __nv_bfloat16 g_gt2  [2048*11264];

// ================= weight conversion: W[K,N] fp32 -> y[N,2K] bf16 hi|lo ====
__global__ void wconv_kernel(const float* __restrict__ W, __nv_bfloat16* __restrict__ y,
                             int K, int N) {
    __shared__ float tile[32][33];
    int n0 = blockIdx.x * 32, k0 = blockIdx.y * 32;
    for (int i = threadIdx.y; i < 32; i += 8)
        tile[i][threadIdx.x] = W[(size_t)(k0 + i) * N + n0 + threadIdx.x];
    __syncthreads();
    for (int i = threadIdx.y; i < 32; i += 8) {
        int n = n0 + i, k = k0 + threadIdx.x;
        float v = tile[threadIdx.x][i];
        size_t base = (size_t)n * 2 * K;
        split_store(v, &y[base + k], &y[base + K + k]);
    }
}

// ================= RMSNorm fused with bf16 split conversion =================
__global__ void rmsconv_kernel(const float* __restrict__ x, const float* __restrict__ w,
                               __nv_bfloat16* __restrict__ y) {
    int row = blockIdx.x;
    const float* xr = x + (size_t)row * HID;
    float s = 0.f;
    for (int i = threadIdx.x; i < HID; i += 256) { float v = xr[i]; s += v * v; }
    __shared__ float red[256];
    red[threadIdx.x] = s; __syncthreads();
    for (int st = 128; st > 0; st >>= 1) {
        if (threadIdx.x < st) red[threadIdx.x] += red[threadIdx.x + st];
        __syncthreads();
    }
    float r = rsqrtf(red[0] / (float)HID + 1e-6f);
    size_t base = (size_t)row * 2 * HID;
    for (int i = threadIdx.x; i < HID; i += 256) {
        float v = w[i] * xr[i] * r;
        split_store(v, &g_ha2[0] + 0, &g_ha2[0] + 0); // placeholder avoided below
        __nv_bfloat16 h = __float2bfloat16(v);
        y[base + i] = h;
        y[base + HID + i] = __float2bfloat16(v - __bfloat162float(h));
    }
}

// ================= bf16 HMMA GEMM (3-segment hi/lo compensated) =================
// C[M,N] fp32 = A x B^T ; A2[M,2K], B2[N,2K] hi|lo splits.
// bias: up to 3 regions [0,n1),[n1,n2),[n2,N) -> b1,b2,b3 (b1 null => no bias)
#define HG_SMEM 65536

__global__ void __launch_bounds__(256, 2) hgemm_kernel(
    const __nv_bfloat16* __restrict__ A, const __nv_bfloat16* __restrict__ B,
    const float* __restrict__ b1, const float* __restrict__ b2, const float* __restrict__ b3,
    int n1, int n2,
    const float* __restrict__ res,
    float* __restrict__ C, int N, int K)
{
    extern __shared__ char smraw[];
    const uint32_t smu = smem_u32(smraw);
    const int tid = threadIdx.x;
    const int lane = tid & 31, wid = tid >> 5;
    const int wm = wid >> 2, wn = wid & 3;
    const size_t lda = 2 * (size_t)K;
    const int kpseg = K >> 6;
    const int nch = 3 * kpseg;
    const size_t arow0 = (size_t)blockIdx.x * 128;
    const size_t brow0 = (size_t)blockIdx.y * 128;

    float acc[4][4][4];
#pragma unroll
    for (int i = 0; i < 4; i++)
#pragma unroll
        for (int j = 0; j < 4; j++)
#pragma unroll
            for (int t = 0; t < 4; t++) acc[i][j][t] = 0.f;

    auto issue = [&](int ch, int b) {
        int seg = ch / kpseg;
        int kk = (ch - seg * kpseg) << 6;
        const __nv_bfloat16* Ab = A + (seg == 1 ? K : 0) + kk;
        const __nv_bfloat16* Bb = B + (seg == 2 ? K : 0) + kk;
        uint32_t abase = smu + b * 32768;
        uint32_t bbase = abase + 16384;
#pragma unroll
        for (int i = 0; i < 4; i++) {
            int u = i * 256 + tid;
            int r = u >> 3, c = u & 7;
            uint32_t so = sw128((uint32_t)(r * 128 + c * 16));
            cp_async16(abase + so, Ab + (arow0 + r) * lda + c * 8);
            cp_async16(bbase + so, Bb + (brow0 + r) * lda + c * 8);
        }
        cp_commit();
    };

    issue(0, 0);

    for (int ch = 0; ch < nch; ch++) {
        const int b = ch & 1;
        if (ch + 1 < nch) {
            issue(ch + 1, b ^ 1);
            asm volatile("cp.async.wait_group 1;");
        } else {
            asm volatile("cp.async.wait_group 0;");
        }
        __syncthreads();

        const uint32_t abuf = smu + b * 32768;
        const uint32_t bbuf = abuf + 16384;
        const int arow = (wm << 6) + (lane & 15);
        const int brow = (wn << 5) + (lane & 15);
        const int kbl = (lane >> 4) * 16;

#pragma unroll
        for (int ks = 0; ks < 4; ks++) {
            const int kb = ks * 32 + kbl;
            uint32_t a[4][4];
#pragma unroll
            for (int mt = 0; mt < 4; mt++) {
                uint32_t off = (uint32_t)((arow + (mt << 4)) * 128 + kb);
                LDSM_X4(a[mt][0], a[mt][1], a[mt][2], a[mt][3], abuf + sw128(off));
            }
            uint32_t bf[4][2];
#pragma unroll
            for (int nt2 = 0; nt2 < 2; nt2++) {
                uint32_t t0, t1, t2, t3;
                uint32_t off = (uint32_t)((brow + (nt2 << 4)) * 128 + kb);
                LDSM_X4(t0, t1, t2, t3, bbuf + sw128(off));
                bf[nt2 * 2 + 0][0] = t0; bf[nt2 * 2 + 0][1] = t2;
                bf[nt2 * 2 + 1][0] = t1; bf[nt2 * 2 + 1][1] = t3;
            }
#pragma unroll
            for (int mt = 0; mt < 4; mt++)
#pragma unroll
                for (int nt = 0; nt < 4; nt++)
                    MMA16816(acc[mt][nt], a[mt], bf[nt][0], bf[nt][1]);
        }
        __syncthreads();
    }

    // epilogue
    const int rbase = (int)arow0 + (wm << 6) + (lane >> 2);
    const int cbase = (int)brow0 + (wn << 5) + ((lane & 3) << 1);
#pragma unroll
    for (int nt = 0; nt < 4; nt++) {
        const int col = cbase + (nt << 3);
        float bv0 = 0.f, bv1 = 0.f;
        if (b1) {
            if (col < n1)       { bv0 = b1[col];      bv1 = b1[col + 1]; }
            else if (col < n2)  { bv0 = b2[col - n1]; bv1 = b2[col - n1 + 1]; }
            else                { bv0 = b3[col - n2]; bv1 = b3[col - n2 + 1]; }
        }
#pragma unroll
        for (int mt = 0; mt < 4; mt++) {
            const int row = rbase + (mt << 4);
            size_t gi = (size_t)row * N + col;
            float v0 = acc[mt][nt][0] + bv0, v1 = acc[mt][nt][1] + bv1;
            if (res) { v0 += res[gi]; v1 += res[gi + 1]; }
            *(float2*)(C + gi) = make_float2(v0, v1);
            size_t gi2 = gi + (size_t)8 * N;
            float v2 = acc[mt][nt][2] + bv0, v3 = acc[mt][nt][3] + bv1;
            if (res) { v2 += res[gi2]; v3 += res[gi2 + 1]; }
            *(float2*)(C + gi2) = make_float2(v2, v3);
        }
    }
}

// ================= small fp32 SGEMM (gate path only) =================
__global__ void __launch_bounds__(256) sgemm_kernel(
    const float* __restrict__ A, const float* __restrict__ B,
    float* __restrict__ C, int M, int N, int K)
{
    __shared__ float As[8][128];
    __shared__ float Bs[8][128];
    const int tid = threadIdx.x;
    const int bx = blockIdx.x * 128;
    const int by = blockIdx.y * 128;
    const int tx = tid & 15;
    const int ty = tid >> 4;
    const int arow = tid >> 1;
    const int acol = (tid & 1) << 2;
    const int brow = tid >> 5;
    const int bcol = (tid & 31) << 2;

    const float* Ap = A + (size_t)(by + arow) * K + acol;
    const float* Bp = B + (size_t)brow * N + bx + bcol;

    float acc[8][8];
#pragma unroll
    for (int i = 0; i < 8; i++)
#pragma unroll
        for (int j = 0; j < 8; j++) acc[i][j] = 0.f;

    for (int k0 = 0; k0 < K; k0 += 8) {
        float4 av = *(const float4*)Ap;
        As[acol + 0][arow] = av.x;
        As[acol + 1][arow] = av.y;
        As[acol + 2][arow] = av.z;
        As[acol + 3][arow] = av.w;
        *(float4*)&Bs[brow][bcol] = *(const float4*)Bp;
        __syncthreads();
#pragma unroll
        for (int kk = 0; kk < 8; kk++) {
            float a[8], bb[8];
            *(float4*)&a[0] = *(const float4*)&As[kk][ty * 8];
            *(float4*)&a[4] = *(const float4*)&As[kk][ty * 8 + 4];
            *(float4*)&bb[0] = *(const float4*)&Bs[kk][tx * 8];
            *(float4*)&bb[4] = *(const float4*)&Bs[kk][tx * 8 + 4];
#pragma unroll
            for (int i = 0; i < 8; i++)
#pragma unroll
                for (int j = 0; j < 8; j++)
                    acc[i][j] += a[i] * bb[j];
        }
        __syncthreads();
        Ap += 8;
        Bp += (size_t)8 * N;
    }

    const int row0 = by + ty * 8;
    const int col0 = bx + tx * 8;
#pragma unroll
    for (int i = 0; i < 8; i++)
#pragma unroll
        for (int j = 0; j < 8; j++)
            C[(size_t)(row0 + i) * N + col0 + j] = acc[i][j];
}

// ================= pooling / gate / rope =================
__global__ void pool_kernel(const float* __restrict__ x, int stride,
                            float* __restrict__ out, int H) {
    int qb = blockIdx.x, h = blockIdx.y, d = threadIdx.x;
    float s = 0.f;
    for (int i = 0; i < BSZ; i++)
        s += x[(size_t)(qb * BSZ + i) * stride + h * DH + d];
    out[((size_t)qb * H + h) * DH + d] = s * (1.f / (float)BSZ);
}

__global__ void gate_kernel(const float* __restrict__ qg, const float* __restrict__ kg,
                            unsigned char* __restrict__ keep) {
    int h = blockIdx.x, qb = blockIdx.y, kb = threadIdx.x;
    const float* qv = qg + ((size_t)qb * HQ + h) * GHD;
    const float* kv = kg + ((size_t)kb * HKV + (h >> 2)) * GHD;
    float s = 0.f;
    for (int d = 0; d < GHD; d++) s += qv[d] * kv[d];
    s *= SCALE_INV_SQRT_128;
    if (kb > qb) s = -1e30f;
    float m = s;
    for (int off = 16; off > 0; off >>= 1)
        m = fmaxf(m, __shfl_xor_sync(0xffffffffu, m, off));
    float e = expf(s - m);
    float sum = e;
    for (int off = 16; off > 0; off >>= 1)
        sum += __shfl_xor_sync(0xffffffffu, sum, off);
    float gate = e / sum;
    bool kp = (kb <= qb) && ((gate >= 0.004f) || (kb == qb));
    keep[((size_t)h * QBN + qb) * QBN + kb] = kp ? 1 : 0;
}

__global__ void rope_kernel(float* __restrict__ x, int stride,
                            const float* __restrict__ cs, const float* __restrict__ sn, int H) {
    int idx = blockIdx.x * blockDim.x + threadIdx.x;
    int d = idx & 63;
    int h = (idx >> 6) % H;
    int s = idx / (64 * H);
    float* p = x + (size_t)s * stride + h * DH;
    float x1 = p[d], x2 = p[d + 64];
    float c1 = cs[(size_t)s * DH + d],      s1 = sn[(size_t)s * DH + d];
    float c2 = cs[(size_t)s * DH + d + 64], s2 = sn[(size_t)s * DH + d + 64];
    p[d]      = x1 * c1 - x2 * s1;
    p[d + 64] = x2 * c2 + x1 * s2;
}

// ================= block-sparse flash attention (fp32), writes bf16 split ====
#define ATTN_SMEM_FLOATS (3 * 64 * 128 + 64 * 64 + 64 * 4 * 2)
__global__ void __launch_bounds__(256) attn_kernel(
    const float* __restrict__ qkv,
    const unsigned char* __restrict__ keep, __nv_bfloat16* __restrict__ oa2)
{
    extern __shared__ float smf[];
    float* Qs   = smf;
    float* Ks   = Qs + 64 * 128;
    float* Vs   = Ks + 64 * 128;
    float* Ps   = Vs + 64 * 128;
    float* redm = Ps + 64 * 64;
    float* redl = redm + 256;

    const int qb = QBN - 1 - blockIdx.x;   // longest CTAs first
    const int h = blockIdx.y;
    const int hk = h >> 2;
    const int tid = threadIdx.x;
    const int r = tid >> 2, c = tid & 3;

    for (int i = tid; i < 64 * 128; i += 256) {
        int rr = i >> 7, dd = i & 127;
        Qs[i] = qkv[(size_t)(qb * 64 + rr) * NQKV + h * DH + dd];
    }

    float m_i = -1e30f, l_i = 0.f;
    float acc[32];
#pragma unroll
    for (int d = 0; d < 32; d++) acc[d] = 0.f;

    const unsigned char* krow = keep + ((size_t)h * QBN + qb) * QBN;

    for (int kb = 0; kb <= qb; kb++) {
        if (!krow[kb]) continue;
        __syncthreads();
        for (int i = tid; i < 64 * 128; i += 256) {
            int rr = i >> 7, dd = i & 127;
            size_t gi = (size_t)(kb * 64 + rr) * NQKV + hk * DH + dd;
            Ks[i] = qkv[gi + 2048];
            Vs[i] = qkv[gi + 2560];
        }
        __syncthreads();

        float sc[16];
        float tmax = -1e30f;
        const float4* q4 = (const float4*)&Qs[r * 128];
#pragma unroll 4
        for (int j = 0; j < 16; j++) {
            int col = c * 16 + j;
            const float4* k4 = (const float4*)&Ks[col * 128];
            float s = 0.f;
#pragma unroll
            for (int d4 = 0; d4 < 32; d4++) {
                float4 a = q4[d4], bb = k4[d4];
                s += a.x * bb.x + a.y * bb.y + a.z * bb.z + a.w * bb.w;
            }
            s *= SCALE_INV_SQRT_128;
            if (kb == qb && col > r) s = -1e30f;
            sc[j] = s;
            tmax = fmaxf(tmax, s);
        }
        redm[r * 4 + c] = tmax;
        __syncthreads();
        float newm = fmaxf(fmaxf(redm[r * 4 + 0], redm[r * 4 + 1]),
                           fmaxf(redm[r * 4 + 2], redm[r * 4 + 3]));
        newm = fmaxf(newm, m_i);
        float lsum = 0.f;
#pragma unroll
        for (int j = 0; j < 16; j++) {
            float p = __expf(sc[j] - newm);
            Ps[r * 64 + c * 16 + j] = p;
            lsum += p;
        }
        redl[r * 4 + c] = lsum;
        float alpha = __expf(m_i - newm);
#pragma unroll
        for (int d = 0; d < 32; d++) acc[d] *= alpha;
        m_i = newm;
        __syncthreads();
        l_i = l_i * alpha + (redl[r * 4 + 0] + redl[r * 4 + 1] +
                             redl[r * 4 + 2] + redl[r * 4 + 3]);
        for (int cc = 0; cc < 64; cc++) {
            float p = Ps[r * 64 + cc];
            const float4* v4 = (const float4*)&Vs[cc * 128 + c * 32];
#pragma unroll
            for (int d4 = 0; d4 < 8; d4++) {
                float4 vv = v4[d4];
                acc[d4 * 4 + 0] += p * vv.x;
                acc[d4 * 4 + 1] += p * vv.y;
                acc[d4 * 4 + 2] += p * vv.z;
                acc[d4 * 4 + 3] += p * vv.w;
            }
        }
    }

    float inv = 1.f / l_i;
    const size_t row = (size_t)(qb * 64 + r);
    const int col0 = h * DH + c * 32;
#pragma unroll
    for (int d = 0; d < 32; d++) {
        float v = acc[d] * inv;
        __nv_bfloat16 hi = __float2bfloat16(v);
        oa2[row * 4096 + col0 + d] = hi;
        oa2[row * 4096 + 2048 + col0 + d] = __float2bfloat16(v - __bfloat162float(hi));
    }
}

// ================= SiLU(gate)*up fused with bf16 split conversion ============
__global__ void siluconv_kernel(const float* __restrict__ gu, __nv_bfloat16* __restrict__ y) {
    int s = blockIdx.y;
    int j = blockIdx.x * 256 + threadIdx.x;
    size_t row = (size_t)s * NGU;
    float x = gu[row + j];
    float u = gu[row + INTER + j];
    float v = (x / (1.f + __expf(-x))) * u;
    __nv_bfloat16 hi = __float2bfloat16(v);
    y[row + j] = hi;
    y[row + INTER + j] = __float2bfloat16(v - __bfloat162float(hi));
}

// ================= launch =================
extern "C" void kernel_launch(void* const* d_in, const int* in_sizes, int n_in,
                              void* d_out, int out_size) {
    const float* hidden = (const float*)d_in[0];
    const float* cosp   = (const float*)d_in[1];
    const float* sinp   = (const float*)d_in[2];
    const float* ln1    = (const float*)d_in[3];
    const float* ln2    = (const float*)d_in[4];
    const float* Wq     = (const float*)d_in[5];
    const float* bq     = (const float*)d_in[6];
    const float* Wk     = (const float*)d_in[7];
    const float* bk     = (const float*)d_in[8];
    const float* Wv     = (const float*)d_in[9];
    const float* bv     = (const float*)d_in[10];
    const float* Wo     = (const float*)d_in[11];
    const float* gWq    = (const float*)d_in[12];
    const float* gWk    = (const float*)d_in[13];
    const float* Wgate  = (const float*)d_in[14];
    const float* Wup    = (const float*)d_in[15];
    const float* Wdown  = (const float*)d_in[16];
    float* out = (float*)d_out;

    float *qkv, *qp, *kp, *qg, *kg, *h2, *gu;
    unsigned char* keep;
    __nv_bfloat16 *Wqkv2, *Wo2, *Wgu2, *Wd2, *ha2, *oa2, *h3a2, *gt2;
    cudaGetSymbolAddress((void**)&qkv,  g_qkv);
    cudaGetSymbolAddress((void**)&qp,   g_qp);
    cudaGetSymbolAddress((void**)&kp,   g_kp);
    cudaGetSymbolAddress((void**)&qg,   g_qg);
    cudaGetSymbolAddress((void**)&kg,   g_kg);
    cudaGetSymbolAddress((void**)&keep, g_keep);
    cudaGetSymbolAddress((void**)&h2,   g_h2);
    cudaGetSymbolAddress((void**)&gu,   g_gu);
    cudaGetSymbolAddress((void**)&Wqkv2, g_Wqkv2);
    cudaGetSymbolAddress((void**)&Wo2,  g_Wo2);
    cudaGetSymbolAddress((void**)&Wgu2, g_Wgu2);
    cudaGetSymbolAddress((void**)&Wd2,  g_Wd2);
    cudaGetSymbolAddress((void**)&ha2,  g_ha2);
    cudaGetSymbolAddress((void**)&oa2,  g_oa2);
    cudaGetSymbolAddress((void**)&h3a2, g_h3a2);
    cudaGetSymbolAddress((void**)&gt2,  g_gt2);

    cudaFuncSetAttribute(hgemm_kernel, cudaFuncAttributeMaxDynamicSharedMemorySize, HG_SMEM);
    cudaFuncSetAttribute(attn_kernel, cudaFuncAttributeMaxDynamicSharedMemorySize,
                         ATTN_SMEM_FLOATS * (int)sizeof(float));

    dim3 w8(32, 8);

    // launches 1-5 (so hgemm is launch #6 for ncu -s 5 -c 1)
    wconv_kernel<<<dim3(HID/32, HID/32), w8>>>(Wq, Wqkv2, HID, HID);                  // 1
    wconv_kernel<<<dim3(512/32, HID/32), w8>>>(Wk, Wqkv2 + (size_t)2048*4096, HID, 512); // 2
    wconv_kernel<<<dim3(512/32, HID/32), w8>>>(Wv, Wqkv2 + (size_t)2560*4096, HID, 512); // 3
    rmsconv_kernel<<<SEQ, 256>>>(hidden, ln1, ha2);                                   // 4
    wconv_kernel<<<dim3(HID/32, HID/32), w8>>>(Wo, Wo2, HID, HID);                    // 5

    // 6: fused QKV projection  (PROFILED LAUNCH)
    hgemm_kernel<<<dim3(SEQ/128, NQKV/128), 256, HG_SMEM>>>(
        ha2, Wqkv2, bq, bk, bv, 2048, 2560, nullptr, qkv, NQKV, HID);

    // gate path
    pool_kernel<<<dim3(QBN, HQ), DH>>>(qkv, NQKV, qp, HQ);
    pool_kernel<<<dim3(QBN, HKV), DH>>>(qkv + 2048, NQKV, kp, HKV);
    sgemm_kernel<<<dim3(GHD/128, (QBN*HQ)/128), 256>>>(qp, gWq, qg, QBN*HQ, GHD, DH);
    sgemm_kernel<<<dim3(GHD/128, (QBN*HKV)/128), 256>>>(kp, gWk, kg, QBN*HKV, GHD, DH);
    gate_kernel<<<dim3(HQ, QBN), 32>>>(qg, kg, keep);

    // RoPE in place (q then k inside qkv)
    rope_kernel<<<(SEQ*HQ*64)/256, 256>>>(qkv, NQKV, cosp, sinp, HQ);
    rope_kernel<<<(SEQ*HKV*64)/256, 256>>>(qkv + 2048, NQKV, cosp, sinp, HKV);

    // block-sparse flash attention -> oa2 (bf16 split)
    attn_kernel<<<dim3(QBN, HQ), 256, ATTN_SMEM_FLOATS * (int)sizeof(float)>>>(qkv, keep, oa2);

    // h2 = o @ Wo + hidden
    hgemm_kernel<<<dim3(SEQ/128, HID/128), 256, HG_SMEM>>>(
        oa2, Wo2, nullptr, nullptr, nullptr, HID, HID, hidden, h2, HID, HQ*DH);

    // h3 = rms(h2)*ln2 -> bf16 split
    rmsconv_kernel<<<SEQ, 256>>>(h2, ln2, h3a2);

    // MLP: fused gate|up GEMM
    wconv_kernel<<<dim3(INTER/32, HID/32), w8>>>(Wgate, Wgu2, HID, INTER);
    wconv_kernel<<<dim3(INTER/32, HID/32), w8>>>(Wup, Wgu2 + (size_t)INTER*4096, HID, INTER);
    hgemm_kernel<<<dim3(SEQ/128, NGU/128), 256, HG_SMEM>>>(
        h3a2, Wgu2, nullptr, nullptr, nullptr, NGU, NGU, nullptr, gu, NGU, HID);

    wconv_kernel<<<dim3(HID/32, INTER/32), w8>>>(Wdown, Wd2, INTER, HID);
    siluconv_kernel<<<dim3(INTER/256, SEQ), 256>>>(gu, gt2);

    // out = silu_mul @ Wdown + h2
    hgemm_kernel<<<dim3(SEQ/128, HID/128), 256, HG_SMEM>>>(
        gt2, Wd2, nullptr, nullptr, nullptr, HID, HID, h2, out, HID, INTER);
}